// round 13
// baseline (speedup 1.0000x reference)
#include <cuda_runtime.h>
#include <cuda_fp16.h>
#include <math.h>
#include <stdint.h>

#define DIMS   2560
#define NH     32
#define HD     80
#define SEQ    2048
#define QKV_N  (3*DIMS)

// ---------------- scratch (static device globals; no runtime allocation) ----
__device__ __half g_xh  [SEQ * DIMS];
__device__ __half g_w1h [QKV_N * DIMS];
__device__ __half g_w2h [DIMS * DIMS];
__device__ __half g_aoh [SEQ * DIMS];     // attention out (fp16)
__device__ __half g_qkvh[SEQ * QKV_N];    // qkv (fp16), rope applied in place

// ============================================================================
// fp32 -> fp16 conversion (vectorized, memory bound)
// ============================================================================
__global__ void cvt_f16_kernel(const float* __restrict__ src,
                               __half* __restrict__ dst, int n4)
{
    int i = blockIdx.x * blockDim.x + threadIdx.x;
    if (i >= n4) return;
    float4 v = ((const float4*)src)[i];
    union { __half h[4]; uint2 u; } H;
    H.h[0] = __float2half_rn(v.x); H.h[1] = __float2half_rn(v.y);
    H.h[2] = __float2half_rn(v.z); H.h[3] = __float2half_rn(v.w);
    ((uint2*)dst)[i] = H.u;
}

// ============================================================================
// PTX helpers (baseline compute_103-safe)
// ============================================================================
__device__ __forceinline__ uint32_t smem_u32(const void* p){
    uint32_t a;
    asm("{ .reg .u64 t; cvta.to.shared.u64 t, %1; cvt.u32.u64 %0, t; }"
        : "=r"(a) : "l"(p));
    return a;
}
__device__ __forceinline__ void cp16(uint32_t dst, const void* src){
    asm volatile("cp.async.ca.shared.global [%0], [%1], 16;"
                 :: "r"(dst), "l"(src) : "memory");
}
__device__ __forceinline__ void cp_commit(){
    asm volatile("cp.async.commit_group;" ::: "memory");
}
template<int N> __device__ __forceinline__ void cp_wait(){
    asm volatile("cp.async.wait_group %0;" :: "n"(N) : "memory");
}
__device__ __forceinline__ void ldm_x4(uint32_t a, uint32_t& r0, uint32_t& r1,
                                       uint32_t& r2, uint32_t& r3){
    asm volatile("ldmatrix.sync.aligned.m8n8.x4.shared.b16 {%0,%1,%2,%3}, [%4];"
                 : "=r"(r0), "=r"(r1), "=r"(r2), "=r"(r3) : "r"(a));
}
__device__ __forceinline__ void ldm_x4_t(uint32_t a, uint32_t& r0, uint32_t& r1,
                                         uint32_t& r2, uint32_t& r3){
    asm volatile("ldmatrix.sync.aligned.m8n8.x4.trans.shared.b16 {%0,%1,%2,%3}, [%4];"
                 : "=r"(r0), "=r"(r1), "=r"(r2), "=r"(r3) : "r"(a));
}
__device__ __forceinline__ void mma_f16(float* c, const uint32_t* a,
                                        uint32_t b0, uint32_t b1){
    asm volatile(
      "mma.sync.aligned.m16n8k16.row.col.f32.f16.f16.f32 "
      "{%0,%1,%2,%3}, {%4,%5,%6,%7}, {%8,%9}, {%0,%1,%2,%3};"
      : "+f"(c[0]), "+f"(c[1]), "+f"(c[2]), "+f"(c[3])
      : "r"(a[0]), "r"(a[1]), "r"(a[2]), "r"(a[3]), "r"(b0), "r"(b1));
}
__device__ __forceinline__ uint32_t pkh(float a, float b){
    __half2 t = __floats2half2_rn(a, b);
    return *(uint32_t*)&t;
}

// ============================================================================
// fp16 tensor-core GEMM: C = A @ B^T + bias.
// CTA 128x128, 4 warps x 64x64, BK=64 (half the barriers), 3-stage cp.async,
// REGISTER fragment double-buffering (ldm latency hidden behind MMA block).
// ============================================================================
#define GBK 64
#define ROWB 144                  // row pitch bytes (128B payload + 16B pad)
#define TILE_B (128 * ROWB)       // 18432 B
#define STAGE_B (2 * TILE_B)      // A, B = 36864 B
#define GM_SMEM (3 * STAGE_B)     // 110592 B, 3 stages
#define GEMM_CTAS 296

__global__ __launch_bounds__(128, 2) void gemm_f16(
    const __half* __restrict__ A, const __half* __restrict__ B,
    const float* __restrict__ bias, float* __restrict__ C,
    __half* __restrict__ Ch,
    int M, int N, int K)
{
    extern __shared__ __align__(16) char smem[];
    const uint32_t sb = smem_u32(smem);

    const int tid  = threadIdx.x;
    const int w    = tid >> 5;
    const int lane = tid & 31;
    const int wm   = (w & 1) * 64;
    const int wn   = (w >> 1) * 64;

    const int tiles_n = N >> 7;
    const int total_tiles = (M >> 7) * tiles_n;

    const int a_row  = lane & 15;
    const int a_koff = (lane >> 4) << 3;
    const int b_row  = (lane & 7) + ((lane >> 4) << 3);
    const int b_koff = ((lane >> 3) & 1) << 3;
    const int nchunks = K / GBK;       // 40

    for (int t = blockIdx.x; t < total_tiles; t += gridDim.x) {
        const int bm = (t / tiles_n) << 7;
        const int bn = (t % tiles_n) << 7;
        const __half* gA = A + (size_t)bm * K;
        const __half* gB = B + (size_t)bn * K;

        auto load_stage = [&](int s, int k0){
            const uint32_t dstb = sb + s * STAGE_B;
            const __half* srcs[2] = { gA, gB };
#pragma unroll
            for (int u = 0; u < 2; u++) {
                const __half* g = srcs[u];
                const uint32_t db = dstb + u * TILE_B;
#pragma unroll
                for (int i = 0; i < 8; i++) {
                    const int idx = i * 128 + tid;   // 1024 16B chunks per tile
                    const int row = idx >> 3;
                    const int kq  = idx & 7;
                    cp16(db + row * ROWB + kq * 16, g + (size_t)row * K + k0 + kq * 8);
                }
            }
            cp_commit();
        };

        float acc[4][8][4];
#pragma unroll
        for (int mt = 0; mt < 4; mt++)
#pragma unroll
            for (int nt = 0; nt < 8; nt++)
#pragma unroll
                for (int r = 0; r < 4; r++) acc[mt][nt][r] = 0.f;

        __syncthreads();            // protect smem reuse across tiles
        load_stage(0, 0);
        load_stage(1, GBK);

        int stage = 0;
        for (int ic = 0; ic < nchunks; ic++) {
            cp_wait<1>();
            __syncthreads();
            if (ic + 2 < nchunks) {
                int s2 = stage + 2; if (s2 >= 3) s2 -= 3;
                load_stage(s2, (ic + 2) * GBK);
            } else {
                cp_commit();        // keep group-count invariant
            }

            const uint32_t st = sb + stage * STAGE_B;
            const uint32_t sA = st;
            const uint32_t sB = st + TILE_B;

            // register fragment double buffer across 4 ks-steps of 16
            uint32_t af[2][4][4], bf[2][4][4];
            auto load_frags = [&](int buf, int ks){
                const int kb = ks * 16;
#pragma unroll
                for (int mt = 0; mt < 4; mt++) {
                    const uint32_t aoff =
                        (uint32_t)((wm + mt * 16 + a_row) * ROWB + (kb + a_koff) * 2);
                    ldm_x4(sA + aoff, af[buf][mt][0], af[buf][mt][1],
                                      af[buf][mt][2], af[buf][mt][3]);
                }
#pragma unroll
                for (int np = 0; np < 4; np++) {
                    const uint32_t boff =
                        (uint32_t)((wn + np * 16 + b_row) * ROWB + (kb + b_koff) * 2);
                    ldm_x4(sB + boff, bf[buf][np][0], bf[buf][np][1],
                                      bf[buf][np][2], bf[buf][np][3]);
                }
            };

            load_frags(0, 0);
#pragma unroll
            for (int ks = 0; ks < 4; ks++) {
                const int cur = ks & 1;
                if (ks < 3) load_frags(cur ^ 1, ks + 1);
#pragma unroll
                for (int np = 0; np < 4; np++) {
#pragma unroll
                    for (int mt = 0; mt < 4; mt++) {
                        mma_f16(acc[mt][2*np],   af[cur][mt], bf[cur][np][0], bf[cur][np][1]);
                        mma_f16(acc[mt][2*np+1], af[cur][mt], bf[cur][np][2], bf[cur][np][3]);
                    }
                }
            }
            stage++; if (stage >= 3) stage -= 3;
        }
        cp_wait<0>();               // drain tail empty groups

#pragma unroll
        for (int mt = 0; mt < 4; mt++) {
            const int r0 = bm + wm + mt * 16 + (lane >> 2);
#pragma unroll
            for (int nt = 0; nt < 8; nt++) {
                const int col = bn + wn + nt * 8 + ((lane & 3) << 1);
                const float2 bv = *(const float2*)&bias[col];
                float v0 = acc[mt][nt][0] + bv.x, v1 = acc[mt][nt][1] + bv.y;
                float v2 = acc[mt][nt][2] + bv.x, v3 = acc[mt][nt][3] + bv.y;
                if (Ch) {
                    *(uint32_t*)(Ch + (size_t)r0       * N + col) = pkh(v0, v1);
                    *(uint32_t*)(Ch + (size_t)(r0 + 8) * N + col) = pkh(v2, v3);
                } else {
                    *(float2*)&C[(size_t)r0       * N + col] = make_float2(v0, v1);
                    *(float2*)&C[(size_t)(r0 + 8) * N + col] = make_float2(v2, v3);
                }
            }
        }
    }
}

// ============================================================================
// RoPE on q and k, in place on fp16 qkv.
// ============================================================================
__global__ void rope_f16_kernel(__half* __restrict__ qkv)
{
    int idx = blockIdx.x * blockDim.x + threadIdx.x;      // SEQ*NH*16 total
    if (idx >= SEQ * NH * 16) return;
    const int d = idx & 15;
    const int h = (idx >> 4) & 31;
    const int t = idx >> 9;

    const float freq  = __expf(-(float)d * 0.5756462732485115f); // ln(1e4)/16
    const float theta = (float)t * freq;
    float s, c;
    sincosf(theta, &s, &c);

    size_t base = (size_t)t * QKV_N + h * HD + d;
#pragma unroll
    for (int qk = 0; qk < 2; qk++) {
        const size_t i1 = base + qk * DIMS;
        const size_t i2 = i1 + 16;
        float x1 = __half2float(qkv[i1]);
        float x2 = __half2float(qkv[i2]);
        qkv[i1] = __float2half_rn(x1 * c - x2 * s);
        qkv[i2] = __float2half_rn(x1 * s + x2 * c);
    }
}

// ============================================================================
// Tensor-core flash attention, causal, fp16 single-term, occupancy 2.
// CTA = (head, 128 q-rows), 256 threads = 8 warps x 16 rows.
// Fully-masked (warp-local) key tiles are skipped entirely.
// ============================================================================
#define AP      88                       // halves per smem row (176B pitch)
#define SQH     0
#define STG0    (128*AP)                 // after Q tile
#define STG_SZ  (2*64*AP)                // KH + VH
#define KH_OFF  0
#define VH_OFF  (64*AP)
#define ATT_SMEM ((STG0 + 2*STG_SZ) * 2) // 67584 bytes

// scale * log2(e): exp(scale*(s-m)) == exp2(C2*(s-m))
#define C2EXP (0.11180339887498949f * 1.4426950408889634f)

__global__ __launch_bounds__(256, 2) void attn_f16(
    const __half* __restrict__ qkvh,
    __half* __restrict__ aoh)
{
    extern __shared__ __align__(16) __half smA[];
    const uint32_t sb = smem_u32(smA);
    const int h  = blockIdx.x;
    const int qb = (gridDim.y - 1) - blockIdx.y;   // heavy tiles first
    const int tid = threadIdx.x, lane = tid & 31, w = tid >> 5;
    const int q0 = qb * 128;

    // ---- Q load (128 rows x 10 col-chunks) ----
    {
        const size_t off = (size_t)q0 * QKV_N + h * HD;
#pragma unroll
        for (int it = 0; it < 5; it++) {
            const int idx = it * 256 + tid;       // 1280 chunks
            const int row = idx / 10, col = idx % 10;
            cp16(sb + (SQH + row * AP) * 2 + col * 16,
                 qkvh + off + (size_t)row * QKV_N + col * 8);
        }
    }
    auto loadKV = [&](int kb, int s){
        const size_t koff = (size_t)(kb * 64) * QKV_N + DIMS + h * HD;
        const uint32_t stg = sb + (STG0 + s * STG_SZ) * 2;
#pragma unroll
        for (int it = 0; it < 3; it++) {
            const int idx = it * 256 + tid;       // 640 (row,col) pairs
            if (idx < 640) {
                const int row = idx / 10, col = idx % 10;
                const size_t gk = koff + (size_t)row * QKV_N + col * 8;
                cp16(stg + (KH_OFF + row * AP) * 2 + col * 16, qkvh + gk);
                cp16(stg + (VH_OFF + row * AP) * 2 + col * 16, qkvh + gk + DIMS);
            }
        }
    };

    float of[10][4];
#pragma unroll
    for (int i = 0; i < 10; i++)
#pragma unroll
        for (int j = 0; j < 4; j++) of[i][j] = 0.f;
    float mA = -1e30f, mB = -1e30f, lA = 0.f, lB = 0.f;   // raw-unit maxima

    loadKV(0, 0);
    cp_commit();

    const int a_row  = lane & 15;
    const int a_k    = (lane >> 4) << 3;
    const int b_row  = (lane & 7) + ((lane >> 4) << 3);
    const int b_k    = ((lane >> 3) & 1) << 3;
    const int vk     = (lane & 7) + (((lane >> 3) & 1) << 3);
    const int vd     = (lane >> 4) << 3;
    const int clb    = 2 * (lane & 3);
    const int rl     = w * 16 + (lane >> 2);   // local q row (A); B = +8

    const int ntiles = 2 * qb + 2;
    for (int kb = 0; kb < ntiles; kb++) {
        cp_wait<0>();
        __syncthreads();
        if (kb + 1 < ntiles) { loadKV(kb + 1, (kb + 1) & 1); cp_commit(); }

        // warp-level full-mask skip: all this warp's rows < first key col
        if (kb * 64 > q0 + w * 16 + 15) continue;

        const uint32_t stg = sb + (STG0 + (kb & 1) * STG_SZ) * 2;

        // ---- S = Q K^T (raw units) ----
        float sf[8][4];
#pragma unroll
        for (int i = 0; i < 8; i++)
#pragma unroll
            for (int j = 0; j < 4; j++) sf[i][j] = 0.f;

#pragma unroll
        for (int kc = 0; kc < 5; kc++) {
            uint32_t aq[4];
            const uint32_t aoff = (uint32_t)((w * 16 + a_row) * AP + kc * 16 + a_k) * 2;
            ldm_x4(sb + SQH * 2 + aoff, aq[0], aq[1], aq[2], aq[3]);
#pragma unroll
            for (int bp = 0; bp < 4; bp++) {
                const uint32_t boff = (uint32_t)((bp * 16 + b_row) * AP + kc * 16 + b_k) * 2;
                uint32_t b0, b1, b2, b3;
                ldm_x4(stg + KH_OFF * 2 + boff, b0, b1, b2, b3);
                mma_f16(sf[2*bp],   aq, b0, b1);
                mma_f16(sf[2*bp+1], aq, b2, b3);
            }
        }

        // ---- causal mask (raw units) ----
        const bool needmask = (kb * 64 + 63 > q0 + w * 16);
        if (needmask) {
#pragma unroll
            for (int nt = 0; nt < 8; nt++) {
                const int c0 = kb * 64 + nt * 8 + clb;
                const int grA = q0 + rl, grB = grA + 8;
#pragma unroll
                for (int j = 0; j < 2; j++) {
                    if (c0 + j > grA) sf[nt][j]     = -1e30f;
                    if (c0 + j > grB) sf[nt][2 + j] = -1e30f;
                }
            }
        }

        // ---- online softmax: raw max + exp2 with folded constant ----
        float mxA = -1e30f, mxB = -1e30f;
#pragma unroll
        for (int nt = 0; nt < 8; nt++) {
            mxA = fmaxf(mxA, fmaxf(sf[nt][0], sf[nt][1]));
            mxB = fmaxf(mxB, fmaxf(sf[nt][2], sf[nt][3]));
        }
        mxA = fmaxf(mxA, __shfl_xor_sync(0xffffffffu, mxA, 1));
        mxA = fmaxf(mxA, __shfl_xor_sync(0xffffffffu, mxA, 2));
        mxB = fmaxf(mxB, __shfl_xor_sync(0xffffffffu, mxB, 1));
        mxB = fmaxf(mxB, __shfl_xor_sync(0xffffffffu, mxB, 2));
        const float mnA = fmaxf(mA, mxA), mnB = fmaxf(mB, mxB);
        const float alphaA = exp2f((mA - mnA) * C2EXP);
        const float alphaB = exp2f((mB - mnB) * C2EXP);
        mA = mnA; mB = mnB;
        const float cA = -mnA * C2EXP, cB = -mnB * C2EXP;

        float sA = 0.f, sB = 0.f;
#pragma unroll
        for (int nt = 0; nt < 8; nt++) {
#pragma unroll
            for (int j = 0; j < 2; j++) {
                float pA = exp2f(fmaf(sf[nt][j],     C2EXP, cA));
                float pB = exp2f(fmaf(sf[nt][2 + j], C2EXP, cB));
                sf[nt][j] = pA; sf[nt][2 + j] = pB;
                sA += pA; sB += pB;
            }
        }
        sA += __shfl_xor_sync(0xffffffffu, sA, 1);
        sA += __shfl_xor_sync(0xffffffffu, sA, 2);
        sB += __shfl_xor_sync(0xffffffffu, sB, 1);
        sB += __shfl_xor_sync(0xffffffffu, sB, 2);
        lA = lA * alphaA + sA;
        lB = lB * alphaB + sB;
#pragma unroll
        for (int d = 0; d < 10; d++) {
            of[d][0] *= alphaA; of[d][1] *= alphaA;
            of[d][2] *= alphaB; of[d][3] *= alphaB;
        }

        // ---- O += P V, P packed to fp16 in registers ----
#pragma unroll
        for (int kc2 = 0; kc2 < 4; kc2++) {
            uint32_t aP[4];
#pragma unroll
            for (int half = 0; half < 2; half++) {
                const int nt = 2 * kc2 + half;
                aP[half * 2 + 0] = pkh(sf[nt][0], sf[nt][1]);
                aP[half * 2 + 1] = pkh(sf[nt][2], sf[nt][3]);
            }
#pragma unroll
            for (int dp = 0; dp < 5; dp++) {
                const uint32_t voff = (uint32_t)((kc2 * 16 + vk) * AP + dp * 16 + vd) * 2;
                uint32_t v0, v1, v2, v3;
                ldm_x4_t(stg + VH_OFF * 2 + voff, v0, v1, v2, v3);
                mma_f16(of[2*dp],   aP, v0, v1);
                mma_f16(of[2*dp+1], aP, v2, v3);
            }
        }
    }

    // ---- epilogue: normalize, store fp16 ----
    const float iA = 1.f / lA, iB = 1.f / lB;
    const int gA = q0 + w * 16 + (lane >> 2);
    const int colb = h * HD + clb;
#pragma unroll
    for (int nt = 0; nt < 10; nt++) {
        const int col = colb + nt * 8;
        *(uint32_t*)(aoh + (size_t)gA * DIMS + col)       =
            pkh(of[nt][0] * iA, of[nt][1] * iA);
        *(uint32_t*)(aoh + (size_t)(gA + 8) * DIMS + col) =
            pkh(of[nt][2] * iB, of[nt][3] * iB);
    }
}

// ============================================================================
extern "C" void kernel_launch(void* const* d_in, const int* in_sizes, int n_in,
                              void* d_out, int out_size)
{
    const float* x       = (const float*)d_in[0];
    const float* Wqkv_w  = (const float*)d_in[1];
    const float* Wqkv_b  = (const float*)d_in[2];
    const float* out_w   = (const float*)d_in[3];
    const float* out_b   = (const float*)d_in[4];
    // d_in[5] = mask: causal triu(-1e9), implemented structurally; unused.
    float* outp = (float*)d_out;

    __half *xh, *w1h, *w2h, *aoh, *qkvh;
    cudaGetSymbolAddress((void**)&xh,   g_xh);
    cudaGetSymbolAddress((void**)&w1h,  g_w1h);
    cudaGetSymbolAddress((void**)&w2h,  g_w2h);
    cudaGetSymbolAddress((void**)&aoh,  g_aoh);
    cudaGetSymbolAddress((void**)&qkvh, g_qkvh);

    cudaFuncSetAttribute(gemm_f16,
                         cudaFuncAttributeMaxDynamicSharedMemorySize, GM_SMEM);
    cudaFuncSetAttribute(attn_f16,
                         cudaFuncAttributeMaxDynamicSharedMemorySize, ATT_SMEM);

    // 0) fp16 conversions of x and weights
    {
        int n4 = (SEQ * DIMS) / 4;
        cvt_f16_kernel<<<(n4 + 255) / 256, 256>>>(x, xh, n4);
        n4 = (QKV_N * DIMS) / 4;
        cvt_f16_kernel<<<(n4 + 255) / 256, 256>>>(Wqkv_w, w1h, n4);
        n4 = (DIMS * DIMS) / 4;
        cvt_f16_kernel<<<(n4 + 255) / 256, 256>>>(out_w, w2h, n4);
    }
    // 1) QKV projection -> fp16 qkv directly (persistent tiles)
    {
        gemm_f16<<<GEMM_CTAS, 128, GM_SMEM>>>(xh, w1h, Wqkv_b, nullptr, qkvh,
                                              SEQ, QKV_N, DIMS);
    }
    // 2) RoPE on q,k (in place, fp16)
    {
        int total = SEQ * NH * 16;
        rope_f16_kernel<<<(total + 255) / 256, 256>>>(qkvh);
    }
    // 3) tensor-core causal flash attention -> fp16 attn out
    {
        dim3 grid(NH, SEQ / 128);
        attn_f16<<<grid, 256, ATT_SMEM>>>(qkvh, aoh);
    }
    // 4) output projection -> fp32 final output (persistent tiles)
    {
        gemm_f16<<<GEMM_CTAS, 128, GM_SMEM>>>(aoh, w2h, out_b, outp, nullptr,
                                              SEQ, DIMS, DIMS);
    }
}

// round 14
// speedup vs baseline: 1.0227x; 1.0227x over previous
#include <cuda_runtime.h>
#include <cuda_fp16.h>
#include <math.h>
#include <stdint.h>

#define DIMS   2560
#define NH     32
#define HD     80
#define SEQ    2048
#define QKV_N  (3*DIMS)

// ---------------- scratch (static device globals; no runtime allocation) ----
__device__ __half g_xh  [SEQ * DIMS];
__device__ __half g_w1h [QKV_N * DIMS];
__device__ __half g_w2h [DIMS * DIMS];
__device__ __half g_aoh [SEQ * DIMS];     // attention out (fp16)
__device__ __half g_qkvh[SEQ * QKV_N];    // qkv (fp16), rope applied in place

// ============================================================================
// Fused fp32 -> fp16 conversion for x, Wqkv_w, out_w in ONE launch.
// Segments (in float4 units): x: 1.31M, w1: 4.915M, w2: 1.6384M
// ============================================================================
#define N4_X  ((SEQ * DIMS) / 4)
#define N4_W1 ((QKV_N * DIMS) / 4)
#define N4_W2 ((DIMS * DIMS) / 4)
#define N4_TOTAL (N4_X + N4_W1 + N4_W2)

__global__ void cvt_all_kernel(const float* __restrict__ x,
                               const float* __restrict__ w1,
                               const float* __restrict__ w2,
                               __half* __restrict__ xh,
                               __half* __restrict__ w1h,
                               __half* __restrict__ w2h)
{
    int i = blockIdx.x * blockDim.x + threadIdx.x;
    if (i >= N4_TOTAL) return;
    const float* src; __half* dst; int j;
    if (i < N4_X)              { src = x;  dst = xh;  j = i; }
    else if (i < N4_X + N4_W1) { src = w1; dst = w1h; j = i - N4_X; }
    else                       { src = w2; dst = w2h; j = i - N4_X - N4_W1; }
    float4 v = ((const float4*)src)[j];
    union { __half h[4]; uint2 u; } H;
    H.h[0] = __float2half_rn(v.x); H.h[1] = __float2half_rn(v.y);
    H.h[2] = __float2half_rn(v.z); H.h[3] = __float2half_rn(v.w);
    ((uint2*)dst)[j] = H.u;
}

// ============================================================================
// PTX helpers (baseline compute_103-safe)
// ============================================================================
__device__ __forceinline__ uint32_t smem_u32(const void* p){
    uint32_t a;
    asm("{ .reg .u64 t; cvta.to.shared.u64 t, %1; cvt.u32.u64 %0, t; }"
        : "=r"(a) : "l"(p));
    return a;
}
__device__ __forceinline__ void cp16(uint32_t dst, const void* src){
    asm volatile("cp.async.cg.shared.global [%0], [%1], 16;"
                 :: "r"(dst), "l"(src) : "memory");
}
__device__ __forceinline__ void cp_commit(){
    asm volatile("cp.async.commit_group;" ::: "memory");
}
template<int N> __device__ __forceinline__ void cp_wait(){
    asm volatile("cp.async.wait_group %0;" :: "n"(N) : "memory");
}
__device__ __forceinline__ void ldm_x4(uint32_t a, uint32_t& r0, uint32_t& r1,
                                       uint32_t& r2, uint32_t& r3){
    asm volatile("ldmatrix.sync.aligned.m8n8.x4.shared.b16 {%0,%1,%2,%3}, [%4];"
                 : "=r"(r0), "=r"(r1), "=r"(r2), "=r"(r3) : "r"(a));
}
__device__ __forceinline__ void ldm_x4_t(uint32_t a, uint32_t& r0, uint32_t& r1,
                                         uint32_t& r2, uint32_t& r3){
    asm volatile("ldmatrix.sync.aligned.m8n8.x4.trans.shared.b16 {%0,%1,%2,%3}, [%4];"
                 : "=r"(r0), "=r"(r1), "=r"(r2), "=r"(r3) : "r"(a));
}
__device__ __forceinline__ void mma_f16(float* c, const uint32_t* a,
                                        uint32_t b0, uint32_t b1){
    asm volatile(
      "mma.sync.aligned.m16n8k16.row.col.f32.f16.f16.f32 "
      "{%0,%1,%2,%3}, {%4,%5,%6,%7}, {%8,%9}, {%0,%1,%2,%3};"
      : "+f"(c[0]), "+f"(c[1]), "+f"(c[2]), "+f"(c[3])
      : "r"(a[0]), "r"(a[1]), "r"(a[2]), "r"(a[3]), "r"(b0), "r"(b1));
}
__device__ __forceinline__ uint32_t pkh(float a, float b){
    __half2 t = __floats2half2_rn(a, b);
    return *(uint32_t*)&t;
}

// ============================================================================
// fp16 tensor-core GEMM (R12 configuration — measured optimum):
// CTA 128x128, 4 warps x 64x64, BK=32, 3-stage cp.async, persistent grid.
// ============================================================================
#define GBK 32
#define TILE_B (128 * 80)        // 128 rows x 80B (64B payload + 16B pad)
#define STAGE_B (2 * TILE_B)     // A, B
#define GM_SMEM (3 * STAGE_B)    // 61440 bytes, 3 stages
#define GEMM_CTAS 296

__global__ __launch_bounds__(128, 2) void gemm_f16(
    const __half* __restrict__ A, const __half* __restrict__ B,
    const float* __restrict__ bias, float* __restrict__ C,
    __half* __restrict__ Ch,
    int M, int N, int K)
{
    extern __shared__ __align__(16) char smem[];
    const uint32_t sb = smem_u32(smem);

    const int tid  = threadIdx.x;
    const int w    = tid >> 5;
    const int lane = tid & 31;
    const int wm   = (w & 1) * 64;
    const int wn   = (w >> 1) * 64;

    const int tiles_n = N >> 7;
    const int total_tiles = (M >> 7) * tiles_n;

    const int a_row  = lane & 15;
    const int a_koff = (lane >> 4) << 3;
    const int b_row  = (lane & 7) + ((lane >> 4) << 3);
    const int b_koff = ((lane >> 3) & 1) << 3;
    const int nchunks = K / GBK;

    for (int t = blockIdx.x; t < total_tiles; t += gridDim.x) {
        const int bm = (t / tiles_n) << 7;
        const int bn = (t % tiles_n) << 7;
        const __half* gA = A + (size_t)bm * K;
        const __half* gB = B + (size_t)bn * K;

        auto load_stage = [&](int s, int k0){
            const uint32_t dstb = sb + s * STAGE_B;
            const __half* srcs[2] = { gA, gB };
#pragma unroll
            for (int u = 0; u < 2; u++) {
                const __half* g = srcs[u];
                const uint32_t db = dstb + u * TILE_B;
#pragma unroll
                for (int i = 0; i < 4; i++) {
                    const int idx = i * 128 + tid;
                    const int row = idx >> 2;
                    const int kq  = idx & 3;
                    cp16(db + row * 80 + kq * 16, g + (size_t)row * K + k0 + kq * 8);
                }
            }
            cp_commit();
        };

        float acc[4][8][4];
#pragma unroll
        for (int mt = 0; mt < 4; mt++)
#pragma unroll
            for (int nt = 0; nt < 8; nt++)
#pragma unroll
                for (int r = 0; r < 4; r++) acc[mt][nt][r] = 0.f;

        __syncthreads();            // protect smem reuse across tiles
        load_stage(0, 0);
        load_stage(1, GBK);

        int stage = 0;
        for (int ic = 0; ic < nchunks; ic++) {
            cp_wait<1>();
            __syncthreads();
            if (ic + 2 < nchunks) {
                int s2 = stage + 2; if (s2 >= 3) s2 -= 3;
                load_stage(s2, (ic + 2) * GBK);
            } else {
                cp_commit();        // keep group-count invariant
            }

            const uint32_t st = sb + stage * STAGE_B;
            const uint32_t sA = st;
            const uint32_t sB = st + TILE_B;

#pragma unroll
            for (int ks = 0; ks < 2; ks++) {
                const int kb = ks * 16;
                uint32_t af[4][4];
#pragma unroll
                for (int mt = 0; mt < 4; mt++) {
                    const uint32_t aoff =
                        (uint32_t)((wm + mt * 16 + a_row) * 80 + (kb + a_koff) * 2);
                    ldm_x4(sA + aoff, af[mt][0], af[mt][1], af[mt][2], af[mt][3]);
                }
#pragma unroll
                for (int np = 0; np < 4; np++) {
                    const uint32_t boff =
                        (uint32_t)((wn + np * 16 + b_row) * 80 + (kb + b_koff) * 2);
                    uint32_t b0, b1, b2, b3;
                    ldm_x4(sB + boff, b0, b1, b2, b3);
#pragma unroll
                    for (int mt = 0; mt < 4; mt++) {
                        mma_f16(acc[mt][2*np],   af[mt], b0, b1);
                        mma_f16(acc[mt][2*np+1], af[mt], b2, b3);
                    }
                }
            }
            stage++; if (stage >= 3) stage -= 3;
        }
        cp_wait<0>();               // drain tail empty group

#pragma unroll
        for (int mt = 0; mt < 4; mt++) {
            const int r0 = bm + wm + mt * 16 + (lane >> 2);
#pragma unroll
            for (int nt = 0; nt < 8; nt++) {
                const int col = bn + wn + nt * 8 + ((lane & 3) << 1);
                const float2 bv = *(const float2*)&bias[col];
                float v0 = acc[mt][nt][0] + bv.x, v1 = acc[mt][nt][1] + bv.y;
                float v2 = acc[mt][nt][2] + bv.x, v3 = acc[mt][nt][3] + bv.y;
                if (Ch) {
                    *(uint32_t*)(Ch + (size_t)r0       * N + col) = pkh(v0, v1);
                    *(uint32_t*)(Ch + (size_t)(r0 + 8) * N + col) = pkh(v2, v3);
                } else {
                    *(float2*)&C[(size_t)r0       * N + col] = make_float2(v0, v1);
                    *(float2*)&C[(size_t)(r0 + 8) * N + col] = make_float2(v2, v3);
                }
            }
        }
    }
}

// ============================================================================
// RoPE on q and k, in place on fp16 qkv.
// ============================================================================
__global__ void rope_f16_kernel(__half* __restrict__ qkv)
{
    int idx = blockIdx.x * blockDim.x + threadIdx.x;      // SEQ*NH*16 total
    if (idx >= SEQ * NH * 16) return;
    const int d = idx & 15;
    const int h = (idx >> 4) & 31;
    const int t = idx >> 9;

    const float freq  = __expf(-(float)d * 0.5756462732485115f); // ln(1e4)/16
    const float theta = (float)t * freq;
    float s, c;
    sincosf(theta, &s, &c);

    size_t base = (size_t)t * QKV_N + h * HD + d;
#pragma unroll
    for (int qk = 0; qk < 2; qk++) {
        const size_t i1 = base + qk * DIMS;
        const size_t i2 = i1 + 16;
        float x1 = __half2float(qkv[i1]);
        float x2 = __half2float(qkv[i2]);
        qkv[i1] = __float2half_rn(x1 * c - x2 * s);
        qkv[i2] = __float2half_rn(x1 * s + x2 * c);
    }
}

// ============================================================================
// Tensor-core flash attention, causal, fp16 single-term, occupancy 2.
// CTA = (head, 128 q-rows), 256 threads = 8 warps x 16 rows.
// Fully-masked (warp-local) key tiles are skipped entirely.
// ============================================================================
#define AP      88                       // halves per smem row (176B pitch)
#define SQH     0
#define STG0    (128*AP)                 // after Q tile
#define STG_SZ  (2*64*AP)                // KH + VH
#define KH_OFF  0
#define VH_OFF  (64*AP)
#define ATT_SMEM ((STG0 + 2*STG_SZ) * 2) // 67584 bytes

// scale * log2(e): exp(scale*(s-m)) == exp2(C2*(s-m))
#define C2EXP (0.11180339887498949f * 1.4426950408889634f)

__global__ __launch_bounds__(256, 2) void attn_f16(
    const __half* __restrict__ qkvh,
    __half* __restrict__ aoh)
{
    extern __shared__ __align__(16) __half smA[];
    const uint32_t sb = smem_u32(smA);
    const int h  = blockIdx.x;
    const int qb = (gridDim.y - 1) - blockIdx.y;   // heavy tiles first
    const int tid = threadIdx.x, lane = tid & 31, w = tid >> 5;
    const int q0 = qb * 128;

    // ---- Q load (128 rows x 10 col-chunks) ----
    {
        const size_t off = (size_t)q0 * QKV_N + h * HD;
#pragma unroll
        for (int it = 0; it < 5; it++) {
            const int idx = it * 256 + tid;       // 1280 chunks
            const int row = idx / 10, col = idx % 10;
            cp16(sb + (SQH + row * AP) * 2 + col * 16,
                 qkvh + off + (size_t)row * QKV_N + col * 8);
        }
    }
    auto loadKV = [&](int kb, int s){
        const size_t koff = (size_t)(kb * 64) * QKV_N + DIMS + h * HD;
        const uint32_t stg = sb + (STG0 + s * STG_SZ) * 2;
#pragma unroll
        for (int it = 0; it < 3; it++) {
            const int idx = it * 256 + tid;       // 640 (row,col) pairs
            if (idx < 640) {
                const int row = idx / 10, col = idx % 10;
                const size_t gk = koff + (size_t)row * QKV_N + col * 8;
                cp16(stg + (KH_OFF + row * AP) * 2 + col * 16, qkvh + gk);
                cp16(stg + (VH_OFF + row * AP) * 2 + col * 16, qkvh + gk + DIMS);
            }
        }
    };

    float of[10][4];
#pragma unroll
    for (int i = 0; i < 10; i++)
#pragma unroll
        for (int j = 0; j < 4; j++) of[i][j] = 0.f;
    float mA = -1e30f, mB = -1e30f, lA = 0.f, lB = 0.f;   // raw-unit maxima

    loadKV(0, 0);
    cp_commit();

    const int a_row  = lane & 15;
    const int a_k    = (lane >> 4) << 3;
    const int b_row  = (lane & 7) + ((lane >> 4) << 3);
    const int b_k    = ((lane >> 3) & 1) << 3;
    const int vk     = (lane & 7) + (((lane >> 3) & 1) << 3);
    const int vd     = (lane >> 4) << 3;
    const int clb    = 2 * (lane & 3);
    const int rl     = w * 16 + (lane >> 2);   // local q row (A); B = +8

    const int ntiles = 2 * qb + 2;
    for (int kb = 0; kb < ntiles; kb++) {
        cp_wait<0>();
        __syncthreads();
        if (kb + 1 < ntiles) { loadKV(kb + 1, (kb + 1) & 1); cp_commit(); }

        // warp-level full-mask skip: all this warp's rows < first key col
        if (kb * 64 > q0 + w * 16 + 15) continue;

        const uint32_t stg = sb + (STG0 + (kb & 1) * STG_SZ) * 2;

        // ---- S = Q K^T (raw units) ----
        float sf[8][4];
#pragma unroll
        for (int i = 0; i < 8; i++)
#pragma unroll
            for (int j = 0; j < 4; j++) sf[i][j] = 0.f;

#pragma unroll
        for (int kc = 0; kc < 5; kc++) {
            uint32_t aq[4];
            const uint32_t aoff = (uint32_t)((w * 16 + a_row) * AP + kc * 16 + a_k) * 2;
            ldm_x4(sb + SQH * 2 + aoff, aq[0], aq[1], aq[2], aq[3]);
#pragma unroll
            for (int bp = 0; bp < 4; bp++) {
                const uint32_t boff = (uint32_t)((bp * 16 + b_row) * AP + kc * 16 + b_k) * 2;
                uint32_t b0, b1, b2, b3;
                ldm_x4(stg + KH_OFF * 2 + boff, b0, b1, b2, b3);
                mma_f16(sf[2*bp],   aq, b0, b1);
                mma_f16(sf[2*bp+1], aq, b2, b3);
            }
        }

        // ---- causal mask (raw units) ----
        const bool needmask = (kb * 64 + 63 > q0 + w * 16);
        if (needmask) {
#pragma unroll
            for (int nt = 0; nt < 8; nt++) {
                const int c0 = kb * 64 + nt * 8 + clb;
                const int grA = q0 + rl, grB = grA + 8;
#pragma unroll
                for (int j = 0; j < 2; j++) {
                    if (c0 + j > grA) sf[nt][j]     = -1e30f;
                    if (c0 + j > grB) sf[nt][2 + j] = -1e30f;
                }
            }
        }

        // ---- online softmax: raw max + exp2 with folded constant ----
        float mxA = -1e30f, mxB = -1e30f;
#pragma unroll
        for (int nt = 0; nt < 8; nt++) {
            mxA = fmaxf(mxA, fmaxf(sf[nt][0], sf[nt][1]));
            mxB = fmaxf(mxB, fmaxf(sf[nt][2], sf[nt][3]));
        }
        mxA = fmaxf(mxA, __shfl_xor_sync(0xffffffffu, mxA, 1));
        mxA = fmaxf(mxA, __shfl_xor_sync(0xffffffffu, mxA, 2));
        mxB = fmaxf(mxB, __shfl_xor_sync(0xffffffffu, mxB, 1));
        mxB = fmaxf(mxB, __shfl_xor_sync(0xffffffffu, mxB, 2));
        const float mnA = fmaxf(mA, mxA), mnB = fmaxf(mB, mxB);
        const float alphaA = exp2f((mA - mnA) * C2EXP);
        const float alphaB = exp2f((mB - mnB) * C2EXP);
        mA = mnA; mB = mnB;
        const float cA = -mnA * C2EXP, cB = -mnB * C2EXP;

        float sA = 0.f, sB = 0.f;
#pragma unroll
        for (int nt = 0; nt < 8; nt++) {
#pragma unroll
            for (int j = 0; j < 2; j++) {
                float pA = exp2f(fmaf(sf[nt][j],     C2EXP, cA));
                float pB = exp2f(fmaf(sf[nt][2 + j], C2EXP, cB));
                sf[nt][j] = pA; sf[nt][2 + j] = pB;
                sA += pA; sB += pB;
            }
        }
        sA += __shfl_xor_sync(0xffffffffu, sA, 1);
        sA += __shfl_xor_sync(0xffffffffu, sA, 2);
        sB += __shfl_xor_sync(0xffffffffu, sB, 1);
        sB += __shfl_xor_sync(0xffffffffu, sB, 2);
        lA = lA * alphaA + sA;
        lB = lB * alphaB + sB;
#pragma unroll
        for (int d = 0; d < 10; d++) {
            of[d][0] *= alphaA; of[d][1] *= alphaA;
            of[d][2] *= alphaB; of[d][3] *= alphaB;
        }

        // ---- O += P V, P packed to fp16 in registers ----
#pragma unroll
        for (int kc2 = 0; kc2 < 4; kc2++) {
            uint32_t aP[4];
#pragma unroll
            for (int half = 0; half < 2; half++) {
                const int nt = 2 * kc2 + half;
                aP[half * 2 + 0] = pkh(sf[nt][0], sf[nt][1]);
                aP[half * 2 + 1] = pkh(sf[nt][2], sf[nt][3]);
            }
#pragma unroll
            for (int dp = 0; dp < 5; dp++) {
                const uint32_t voff = (uint32_t)((kc2 * 16 + vk) * AP + dp * 16 + vd) * 2;
                uint32_t v0, v1, v2, v3;
                ldm_x4_t(stg + VH_OFF * 2 + voff, v0, v1, v2, v3);
                mma_f16(of[2*dp],   aP, v0, v1);
                mma_f16(of[2*dp+1], aP, v2, v3);
            }
        }
    }

    // ---- epilogue: normalize, store fp16 ----
    const float iA = 1.f / lA, iB = 1.f / lB;
    const int gA = q0 + w * 16 + (lane >> 2);
    const int colb = h * HD + clb;
#pragma unroll
    for (int nt = 0; nt < 10; nt++) {
        const int col = colb + nt * 8;
        *(uint32_t*)(aoh + (size_t)gA * DIMS + col)       =
            pkh(of[nt][0] * iA, of[nt][1] * iA);
        *(uint32_t*)(aoh + (size_t)(gA + 8) * DIMS + col) =
            pkh(of[nt][2] * iB, of[nt][3] * iB);
    }
}

// ============================================================================
extern "C" void kernel_launch(void* const* d_in, const int* in_sizes, int n_in,
                              void* d_out, int out_size)
{
    const float* x       = (const float*)d_in[0];
    const float* Wqkv_w  = (const float*)d_in[1];
    const float* Wqkv_b  = (const float*)d_in[2];
    const float* out_w   = (const float*)d_in[3];
    const float* out_b   = (const float*)d_in[4];
    // d_in[5] = mask: causal triu(-1e9), implemented structurally; unused.
    float* outp = (float*)d_out;

    __half *xh, *w1h, *w2h, *aoh, *qkvh;
    cudaGetSymbolAddress((void**)&xh,   g_xh);
    cudaGetSymbolAddress((void**)&w1h,  g_w1h);
    cudaGetSymbolAddress((void**)&w2h,  g_w2h);
    cudaGetSymbolAddress((void**)&aoh,  g_aoh);
    cudaGetSymbolAddress((void**)&qkvh, g_qkvh);

    cudaFuncSetAttribute(gemm_f16,
                         cudaFuncAttributeMaxDynamicSharedMemorySize, GM_SMEM);
    cudaFuncSetAttribute(attn_f16,
                         cudaFuncAttributeMaxDynamicSharedMemorySize, ATT_SMEM);

    // 0) fused fp16 conversions of x and both weights (single launch)
    {
        cvt_all_kernel<<<(N4_TOTAL + 255) / 256, 256>>>(x, Wqkv_w, out_w,
                                                        xh, w1h, w2h);
    }
    // 1) QKV projection -> fp16 qkv directly (persistent tiles)
    {
        gemm_f16<<<GEMM_CTAS, 128, GM_SMEM>>>(xh, w1h, Wqkv_b, nullptr, qkvh,
                                              SEQ, QKV_N, DIMS);
    }
    // 2) RoPE on q,k (in place, fp16)
    {
        int total = SEQ * NH * 16;
        rope_f16_kernel<<<(total + 255) / 256, 256>>>(qkvh);
    }
    // 3) tensor-core causal flash attention -> fp16 attn out
    {
        dim3 grid(NH, SEQ / 128);
        attn_f16<<<grid, 256, ATT_SMEM>>>(qkvh, aoh);
    }
    // 4) output projection -> fp32 final output (persistent tiles)
    {
        gemm_f16<<<GEMM_CTAS, 128, GM_SMEM>>>(aoh, w2h, out_b, outp, nullptr,
                                              SEQ, DIMS, DIMS);
    }
}

// round 15
// speedup vs baseline: 1.1280x; 1.1029x over previous
#include <cuda_runtime.h>
#include <cuda_fp16.h>
#include <math.h>
#include <stdint.h>

#define DIMS   2560
#define NH     32
#define HD     80
#define SEQ    2048
#define QKV_N  (3*DIMS)

// ---------------- scratch (static device globals; no runtime allocation) ----
__device__ __half g_xh  [SEQ * DIMS];
__device__ __half g_w1h [QKV_N * DIMS];
__device__ __half g_w2h [DIMS * DIMS];
__device__ __half g_aoh [SEQ * DIMS];     // attention out (fp16)
__device__ __half g_qkvh[SEQ * QKV_N];    // qkv (fp16), rope applied in place

// ============================================================================
// Fused fp32 -> fp16 conversion for x, Wqkv_w, out_w in ONE launch.
// ============================================================================
#define N4_X  ((SEQ * DIMS) / 4)
#define N4_W1 ((QKV_N * DIMS) / 4)
#define N4_W2 ((DIMS * DIMS) / 4)
#define N4_TOTAL (N4_X + N4_W1 + N4_W2)

__global__ void cvt_all_kernel(const float* __restrict__ x,
                               const float* __restrict__ w1,
                               const float* __restrict__ w2,
                               __half* __restrict__ xh,
                               __half* __restrict__ w1h,
                               __half* __restrict__ w2h)
{
    int i = blockIdx.x * blockDim.x + threadIdx.x;
    if (i >= N4_TOTAL) return;
    const float* src; __half* dst; int j;
    if (i < N4_X)              { src = x;  dst = xh;  j = i; }
    else if (i < N4_X + N4_W1) { src = w1; dst = w1h; j = i - N4_X; }
    else                       { src = w2; dst = w2h; j = i - N4_X - N4_W1; }
    float4 v = ((const float4*)src)[j];
    union { __half h[4]; uint2 u; } H;
    H.h[0] = __float2half_rn(v.x); H.h[1] = __float2half_rn(v.y);
    H.h[2] = __float2half_rn(v.z); H.h[3] = __float2half_rn(v.w);
    ((uint2*)dst)[j] = H.u;
}

// ============================================================================
// PTX helpers (baseline compute_103-safe)
// ============================================================================
__device__ __forceinline__ uint32_t smem_u32(const void* p){
    uint32_t a;
    asm("{ .reg .u64 t; cvta.to.shared.u64 t, %1; cvt.u32.u64 %0, t; }"
        : "=r"(a) : "l"(p));
    return a;
}
__device__ __forceinline__ void cp16(uint32_t dst, const void* src){
    asm volatile("cp.async.ca.shared.global [%0], [%1], 16;"
                 :: "r"(dst), "l"(src) : "memory");
}
__device__ __forceinline__ void cp_commit(){
    asm volatile("cp.async.commit_group;" ::: "memory");
}
template<int N> __device__ __forceinline__ void cp_wait(){
    asm volatile("cp.async.wait_group %0;" :: "n"(N) : "memory");
}
__device__ __forceinline__ void ldm_x4(uint32_t a, uint32_t& r0, uint32_t& r1,
                                       uint32_t& r2, uint32_t& r3){
    asm volatile("ldmatrix.sync.aligned.m8n8.x4.shared.b16 {%0,%1,%2,%3}, [%4];"
                 : "=r"(r0), "=r"(r1), "=r"(r2), "=r"(r3) : "r"(a));
}
__device__ __forceinline__ void ldm_x4_t(uint32_t a, uint32_t& r0, uint32_t& r1,
                                         uint32_t& r2, uint32_t& r3){
    asm volatile("ldmatrix.sync.aligned.m8n8.x4.trans.shared.b16 {%0,%1,%2,%3}, [%4];"
                 : "=r"(r0), "=r"(r1), "=r"(r2), "=r"(r3) : "r"(a));
}
__device__ __forceinline__ void mma_f16(float* c, const uint32_t* a,
                                        uint32_t b0, uint32_t b1){
    asm volatile(
      "mma.sync.aligned.m16n8k16.row.col.f32.f16.f16.f32 "
      "{%0,%1,%2,%3}, {%4,%5,%6,%7}, {%8,%9}, {%0,%1,%2,%3};"
      : "+f"(c[0]), "+f"(c[1]), "+f"(c[2]), "+f"(c[3])
      : "r"(a[0]), "r"(a[1]), "r"(a[2]), "r"(a[3]), "r"(b0), "r"(b1));
}
__device__ __forceinline__ uint32_t pkh(float a, float b){
    __half2 t = __floats2half2_rn(a, b);
    return *(uint32_t*)&t;
}

// ============================================================================
// fp16 tensor-core GEMM (R12 configuration — measured optimum):
// CTA 128x128, 4 warps x 64x64, BK=32, 3-stage cp.async (.ca), persistent.
// ============================================================================
#define GBK 32
#define TILE_B (128 * 80)        // 128 rows x 80B (64B payload + 16B pad)
#define STAGE_B (2 * TILE_B)     // A, B
#define GM_SMEM (3 * STAGE_B)    // 61440 bytes, 3 stages
#define GEMM_CTAS 296

__global__ __launch_bounds__(128, 2) void gemm_f16(
    const __half* __restrict__ A, const __half* __restrict__ B,
    const float* __restrict__ bias, float* __restrict__ C,
    __half* __restrict__ Ch,
    int M, int N, int K)
{
    extern __shared__ __align__(16) char smem[];
    const uint32_t sb = smem_u32(smem);

    const int tid  = threadIdx.x;
    const int w    = tid >> 5;
    const int lane = tid & 31;
    const int wm   = (w & 1) * 64;
    const int wn   = (w >> 1) * 64;

    const int tiles_n = N >> 7;
    const int total_tiles = (M >> 7) * tiles_n;

    const int a_row  = lane & 15;
    const int a_koff = (lane >> 4) << 3;
    const int b_row  = (lane & 7) + ((lane >> 4) << 3);
    const int b_koff = ((lane >> 3) & 1) << 3;
    const int nchunks = K / GBK;

    for (int t = blockIdx.x; t < total_tiles; t += gridDim.x) {
        const int bm = (t / tiles_n) << 7;
        const int bn = (t % tiles_n) << 7;
        const __half* gA = A + (size_t)bm * K;
        const __half* gB = B + (size_t)bn * K;

        auto load_stage = [&](int s, int k0){
            const uint32_t dstb = sb + s * STAGE_B;
            const __half* srcs[2] = { gA, gB };
#pragma unroll
            for (int u = 0; u < 2; u++) {
                const __half* g = srcs[u];
                const uint32_t db = dstb + u * TILE_B;
#pragma unroll
                for (int i = 0; i < 4; i++) {
                    const int idx = i * 128 + tid;
                    const int row = idx >> 2;
                    const int kq  = idx & 3;
                    cp16(db + row * 80 + kq * 16, g + (size_t)row * K + k0 + kq * 8);
                }
            }
            cp_commit();
        };

        float acc[4][8][4];
#pragma unroll
        for (int mt = 0; mt < 4; mt++)
#pragma unroll
            for (int nt = 0; nt < 8; nt++)
#pragma unroll
                for (int r = 0; r < 4; r++) acc[mt][nt][r] = 0.f;

        __syncthreads();            // protect smem reuse across tiles
        load_stage(0, 0);
        load_stage(1, GBK);

        int stage = 0;
        for (int ic = 0; ic < nchunks; ic++) {
            cp_wait<1>();
            __syncthreads();
            if (ic + 2 < nchunks) {
                int s2 = stage + 2; if (s2 >= 3) s2 -= 3;
                load_stage(s2, (ic + 2) * GBK);
            } else {
                cp_commit();        // keep group-count invariant
            }

            const uint32_t st = sb + stage * STAGE_B;
            const uint32_t sA = st;
            const uint32_t sB = st + TILE_B;

#pragma unroll
            for (int ks = 0; ks < 2; ks++) {
                const int kb = ks * 16;
                uint32_t af[4][4];
#pragma unroll
                for (int mt = 0; mt < 4; mt++) {
                    const uint32_t aoff =
                        (uint32_t)((wm + mt * 16 + a_row) * 80 + (kb + a_koff) * 2);
                    ldm_x4(sA + aoff, af[mt][0], af[mt][1], af[mt][2], af[mt][3]);
                }
#pragma unroll
                for (int np = 0; np < 4; np++) {
                    const uint32_t boff =
                        (uint32_t)((wn + np * 16 + b_row) * 80 + (kb + b_koff) * 2);
                    uint32_t b0, b1, b2, b3;
                    ldm_x4(sB + boff, b0, b1, b2, b3);
#pragma unroll
                    for (int mt = 0; mt < 4; mt++) {
                        mma_f16(acc[mt][2*np],   af[mt], b0, b1);
                        mma_f16(acc[mt][2*np+1], af[mt], b2, b3);
                    }
                }
            }
            stage++; if (stage >= 3) stage -= 3;
        }
        cp_wait<0>();               // drain tail empty group

#pragma unroll
        for (int mt = 0; mt < 4; mt++) {
            const int r0 = bm + wm + mt * 16 + (lane >> 2);
#pragma unroll
            for (int nt = 0; nt < 8; nt++) {
                const int col = bn + wn + nt * 8 + ((lane & 3) << 1);
                const float2 bv = *(const float2*)&bias[col];
                float v0 = acc[mt][nt][0] + bv.x, v1 = acc[mt][nt][1] + bv.y;
                float v2 = acc[mt][nt][2] + bv.x, v3 = acc[mt][nt][3] + bv.y;
                if (Ch) {
                    *(uint32_t*)(Ch + (size_t)r0       * N + col) = pkh(v0, v1);
                    *(uint32_t*)(Ch + (size_t)(r0 + 8) * N + col) = pkh(v2, v3);
                } else {
                    *(float2*)&C[(size_t)r0       * N + col] = make_float2(v0, v1);
                    *(float2*)&C[(size_t)(r0 + 8) * N + col] = make_float2(v2, v3);
                }
            }
        }
    }
}

// ============================================================================
// RoPE on q and k, in place on fp16 qkv.
// ============================================================================
__global__ void rope_f16_kernel(__half* __restrict__ qkv)
{
    int idx = blockIdx.x * blockDim.x + threadIdx.x;      // SEQ*NH*16 total
    if (idx >= SEQ * NH * 16) return;
    const int d = idx & 15;
    const int h = (idx >> 4) & 31;
    const int t = idx >> 9;

    const float freq  = __expf(-(float)d * 0.5756462732485115f); // ln(1e4)/16
    const float theta = (float)t * freq;
    float s, c;
    sincosf(theta, &s, &c);

    size_t base = (size_t)t * QKV_N + h * HD + d;
#pragma unroll
    for (int qk = 0; qk < 2; qk++) {
        const size_t i1 = base + qk * DIMS;
        const size_t i2 = i1 + 16;
        float x1 = __half2float(qkv[i1]);
        float x2 = __half2float(qkv[i2]);
        qkv[i1] = __float2half_rn(x1 * c - x2 * s);
        qkv[i2] = __float2half_rn(x1 * s + x2 * c);
    }
}

// ============================================================================
// Tensor-core flash attention, causal, fp16 single-term, occupancy 2.
// CTA = (head, 128 q-rows), 256 threads = 8 warps x 16 rows.
// Fully-masked (warp-local) key tiles are skipped entirely.
// ============================================================================
#define AP      88                       // halves per smem row (176B pitch)
#define SQH     0
#define STG0    (128*AP)                 // after Q tile
#define STG_SZ  (2*64*AP)                // KH + VH
#define KH_OFF  0
#define VH_OFF  (64*AP)
#define ATT_SMEM ((STG0 + 2*STG_SZ) * 2) // 67584 bytes

// scale * log2(e): exp(scale*(s-m)) == exp2(C2*(s-m))
#define C2EXP (0.11180339887498949f * 1.4426950408889634f)

__global__ __launch_bounds__(256, 2) void attn_f16(
    const __half* __restrict__ qkvh,
    __half* __restrict__ aoh)
{
    extern __shared__ __align__(16) __half smA[];
    const uint32_t sb = smem_u32(smA);
    const int h  = blockIdx.x;
    const int qb = (gridDim.y - 1) - blockIdx.y;   // heavy tiles first
    const int tid = threadIdx.x, lane = tid & 31, w = tid >> 5;
    const int q0 = qb * 128;

    // ---- Q load (128 rows x 10 col-chunks) ----
    {
        const size_t off = (size_t)q0 * QKV_N + h * HD;
#pragma unroll
        for (int it = 0; it < 5; it++) {
            const int idx = it * 256 + tid;       // 1280 chunks
            const int row = idx / 10, col = idx % 10;
            cp16(sb + (SQH + row * AP) * 2 + col * 16,
                 qkvh + off + (size_t)row * QKV_N + col * 8);
        }
    }
    auto loadKV = [&](int kb, int s){
        const size_t koff = (size_t)(kb * 64) * QKV_N + DIMS + h * HD;
        const uint32_t stg = sb + (STG0 + s * STG_SZ) * 2;
#pragma unroll
        for (int it = 0; it < 3; it++) {
            const int idx = it * 256 + tid;       // 640 (row,col) pairs
            if (idx < 640) {
                const int row = idx / 10, col = idx % 10;
                const size_t gk = koff + (size_t)row * QKV_N + col * 8;
                cp16(stg + (KH_OFF + row * AP) * 2 + col * 16, qkvh + gk);
                cp16(stg + (VH_OFF + row * AP) * 2 + col * 16, qkvh + gk + DIMS);
            }
        }
    };

    float of[10][4];
#pragma unroll
    for (int i = 0; i < 10; i++)
#pragma unroll
        for (int j = 0; j < 4; j++) of[i][j] = 0.f;
    float mA = -1e30f, mB = -1e30f, lA = 0.f, lB = 0.f;   // raw-unit maxima

    loadKV(0, 0);
    cp_commit();

    const int a_row  = lane & 15;
    const int a_k    = (lane >> 4) << 3;
    const int b_row  = (lane & 7) + ((lane >> 4) << 3);
    const int b_k    = ((lane >> 3) & 1) << 3;
    const int vk     = (lane & 7) + (((lane >> 3) & 1) << 3);
    const int vd     = (lane >> 4) << 3;
    const int clb    = 2 * (lane & 3);
    const int rl     = w * 16 + (lane >> 2);   // local q row (A); B = +8

    const int ntiles = 2 * qb + 2;
    for (int kb = 0; kb < ntiles; kb++) {
        cp_wait<0>();
        __syncthreads();
        if (kb + 1 < ntiles) { loadKV(kb + 1, (kb + 1) & 1); cp_commit(); }

        // warp-level full-mask skip: all this warp's rows < first key col
        if (kb * 64 > q0 + w * 16 + 15) continue;

        const uint32_t stg = sb + (STG0 + (kb & 1) * STG_SZ) * 2;

        // ---- S = Q K^T (raw units) ----
        float sf[8][4];
#pragma unroll
        for (int i = 0; i < 8; i++)
#pragma unroll
            for (int j = 0; j < 4; j++) sf[i][j] = 0.f;

#pragma unroll
        for (int kc = 0; kc < 5; kc++) {
            uint32_t aq[4];
            const uint32_t aoff = (uint32_t)((w * 16 + a_row) * AP + kc * 16 + a_k) * 2;
            ldm_x4(sb + SQH * 2 + aoff, aq[0], aq[1], aq[2], aq[3]);
#pragma unroll
            for (int bp = 0; bp < 4; bp++) {
                const uint32_t boff = (uint32_t)((bp * 16 + b_row) * AP + kc * 16 + b_k) * 2;
                uint32_t b0, b1, b2, b3;
                ldm_x4(stg + KH_OFF * 2 + boff, b0, b1, b2, b3);
                mma_f16(sf[2*bp],   aq, b0, b1);
                mma_f16(sf[2*bp+1], aq, b2, b3);
            }
        }

        // ---- causal mask (raw units) ----
        const bool needmask = (kb * 64 + 63 > q0 + w * 16);
        if (needmask) {
#pragma unroll
            for (int nt = 0; nt < 8; nt++) {
                const int c0 = kb * 64 + nt * 8 + clb;
                const int grA = q0 + rl, grB = grA + 8;
#pragma unroll
                for (int j = 0; j < 2; j++) {
                    if (c0 + j > grA) sf[nt][j]     = -1e30f;
                    if (c0 + j > grB) sf[nt][2 + j] = -1e30f;
                }
            }
        }

        // ---- online softmax: raw max + exp2 with folded constant ----
        float mxA = -1e30f, mxB = -1e30f;
#pragma unroll
        for (int nt = 0; nt < 8; nt++) {
            mxA = fmaxf(mxA, fmaxf(sf[nt][0], sf[nt][1]));
            mxB = fmaxf(mxB, fmaxf(sf[nt][2], sf[nt][3]));
        }
        mxA = fmaxf(mxA, __shfl_xor_sync(0xffffffffu, mxA, 1));
        mxA = fmaxf(mxA, __shfl_xor_sync(0xffffffffu, mxA, 2));
        mxB = fmaxf(mxB, __shfl_xor_sync(0xffffffffu, mxB, 1));
        mxB = fmaxf(mxB, __shfl_xor_sync(0xffffffffu, mxB, 2));
        const float mnA = fmaxf(mA, mxA), mnB = fmaxf(mB, mxB);
        const float alphaA = exp2f((mA - mnA) * C2EXP);
        const float alphaB = exp2f((mB - mnB) * C2EXP);
        mA = mnA; mB = mnB;
        const float cA = -mnA * C2EXP, cB = -mnB * C2EXP;

        float sA = 0.f, sB = 0.f;
#pragma unroll
        for (int nt = 0; nt < 8; nt++) {
#pragma unroll
            for (int j = 0; j < 2; j++) {
                float pA = exp2f(fmaf(sf[nt][j],     C2EXP, cA));
                float pB = exp2f(fmaf(sf[nt][2 + j], C2EXP, cB));
                sf[nt][j] = pA; sf[nt][2 + j] = pB;
                sA += pA; sB += pB;
            }
        }
        sA += __shfl_xor_sync(0xffffffffu, sA, 1);
        sA += __shfl_xor_sync(0xffffffffu, sA, 2);
        sB += __shfl_xor_sync(0xffffffffu, sB, 1);
        sB += __shfl_xor_sync(0xffffffffu, sB, 2);
        lA = lA * alphaA + sA;
        lB = lB * alphaB + sB;
#pragma unroll
        for (int d = 0; d < 10; d++) {
            of[d][0] *= alphaA; of[d][1] *= alphaA;
            of[d][2] *= alphaB; of[d][3] *= alphaB;
        }

        // ---- O += P V, P packed to fp16 in registers ----
#pragma unroll
        for (int kc2 = 0; kc2 < 4; kc2++) {
            uint32_t aP[4];
#pragma unroll
            for (int half = 0; half < 2; half++) {
                const int nt = 2 * kc2 + half;
                aP[half * 2 + 0] = pkh(sf[nt][0], sf[nt][1]);
                aP[half * 2 + 1] = pkh(sf[nt][2], sf[nt][3]);
            }
#pragma unroll
            for (int dp = 0; dp < 5; dp++) {
                const uint32_t voff = (uint32_t)((kc2 * 16 + vk) * AP + dp * 16 + vd) * 2;
                uint32_t v0, v1, v2, v3;
                ldm_x4_t(stg + VH_OFF * 2 + voff, v0, v1, v2, v3);
                mma_f16(of[2*dp],   aP, v0, v1);
                mma_f16(of[2*dp+1], aP, v2, v3);
            }
        }
    }

    // ---- epilogue: normalize, store fp16 ----
    const float iA = 1.f / lA, iB = 1.f / lB;
    const int gA = q0 + w * 16 + (lane >> 2);
    const int colb = h * HD + clb;
#pragma unroll
    for (int nt = 0; nt < 10; nt++) {
        const int col = colb + nt * 8;
        *(uint32_t*)(aoh + (size_t)gA * DIMS + col)       =
            pkh(of[nt][0] * iA, of[nt][1] * iA);
        *(uint32_t*)(aoh + (size_t)(gA + 8) * DIMS + col) =
            pkh(of[nt][2] * iB, of[nt][3] * iB);
    }
}

// ============================================================================
extern "C" void kernel_launch(void* const* d_in, const int* in_sizes, int n_in,
                              void* d_out, int out_size)
{
    const float* x       = (const float*)d_in[0];
    const float* Wqkv_w  = (const float*)d_in[1];
    const float* Wqkv_b  = (const float*)d_in[2];
    const float* out_w   = (const float*)d_in[3];
    const float* out_b   = (const float*)d_in[4];
    // d_in[5] = mask: causal triu(-1e9), implemented structurally; unused.
    float* outp = (float*)d_out;

    __half *xh, *w1h, *w2h, *aoh, *qkvh;
    cudaGetSymbolAddress((void**)&xh,   g_xh);
    cudaGetSymbolAddress((void**)&w1h,  g_w1h);
    cudaGetSymbolAddress((void**)&w2h,  g_w2h);
    cudaGetSymbolAddress((void**)&aoh,  g_aoh);
    cudaGetSymbolAddress((void**)&qkvh, g_qkvh);

    cudaFuncSetAttribute(gemm_f16,
                         cudaFuncAttributeMaxDynamicSharedMemorySize, GM_SMEM);
    cudaFuncSetAttribute(attn_f16,
                         cudaFuncAttributeMaxDynamicSharedMemorySize, ATT_SMEM);

    // 0) fused fp16 conversions of x and both weights (single launch)
    {
        cvt_all_kernel<<<(N4_TOTAL + 255) / 256, 256>>>(x, Wqkv_w, out_w,
                                                        xh, w1h, w2h);
    }
    // 1) QKV projection -> fp16 qkv directly (persistent tiles)
    {
        gemm_f16<<<GEMM_CTAS, 128, GM_SMEM>>>(xh, w1h, Wqkv_b, nullptr, qkvh,
                                              SEQ, QKV_N, DIMS);
    }
    // 2) RoPE on q,k (in place, fp16)
    {
        int total = SEQ * NH * 16;
        rope_f16_kernel<<<(total + 255) / 256, 256>>>(qkvh);
    }
    // 3) tensor-core causal flash attention -> fp16 attn out
    {
        dim3 grid(NH, SEQ / 128);
        attn_f16<<<grid, 256, ATT_SMEM>>>(qkvh, aoh);
    }
    // 4) output projection -> fp32 final output (persistent tiles)
    {
        gemm_f16<<<GEMM_CTAS, 128, GM_SMEM>>>(aoh, w2h, out_b, outp, nullptr,
                                              SEQ, DIMS, DIMS);
    }
}

// round 16
// speedup vs baseline: 1.1454x; 1.0155x over previous
#include <cuda_runtime.h>
#include <cuda_fp16.h>
#include <math.h>
#include <stdint.h>

#define DIMS   2560
#define NH     32
#define HD     80
#define SEQ    2048
#define QKV_N  (3*DIMS)

// ---------------- scratch (static device globals; no runtime allocation) ----
__device__ __half g_xh  [SEQ * DIMS];
__device__ __half g_w1h [QKV_N * DIMS];
__device__ __half g_w2h [DIMS * DIMS];
__device__ __half g_aoh [SEQ * DIMS];     // attention out (fp16)
__device__ __half g_qkvh[SEQ * QKV_N];    // qkv (fp16), rope applied in place

// ============================================================================
// Fused fp32 -> fp16 conversion for x, Wqkv_w, out_w in ONE launch.
// ============================================================================
#define N4_X  ((SEQ * DIMS) / 4)
#define N4_W1 ((QKV_N * DIMS) / 4)
#define N4_W2 ((DIMS * DIMS) / 4)
#define N4_TOTAL (N4_X + N4_W1 + N4_W2)

__global__ void cvt_all_kernel(const float* __restrict__ x,
                               const float* __restrict__ w1,
                               const float* __restrict__ w2,
                               __half* __restrict__ xh,
                               __half* __restrict__ w1h,
                               __half* __restrict__ w2h)
{
    int i = blockIdx.x * blockDim.x + threadIdx.x;
    if (i >= N4_TOTAL) return;
    const float* src; __half* dst; int j;
    if (i < N4_X)              { src = x;  dst = xh;  j = i; }
    else if (i < N4_X + N4_W1) { src = w1; dst = w1h; j = i - N4_X; }
    else                       { src = w2; dst = w2h; j = i - N4_X - N4_W1; }
    float4 v = ((const float4*)src)[j];
    union { __half h[4]; uint2 u; } H;
    H.h[0] = __float2half_rn(v.x); H.h[1] = __float2half_rn(v.y);
    H.h[2] = __float2half_rn(v.z); H.h[3] = __float2half_rn(v.w);
    ((uint2*)dst)[j] = H.u;
}

// ============================================================================
// PTX helpers (baseline compute_103-safe)
// ============================================================================
__device__ __forceinline__ uint32_t smem_u32(const void* p){
    uint32_t a;
    asm("{ .reg .u64 t; cvta.to.shared.u64 t, %1; cvt.u32.u64 %0, t; }"
        : "=r"(a) : "l"(p));
    return a;
}
__device__ __forceinline__ void cp16(uint32_t dst, const void* src){
    asm volatile("cp.async.ca.shared.global [%0], [%1], 16;"
                 :: "r"(dst), "l"(src) : "memory");
}
__device__ __forceinline__ void cp_commit(){
    asm volatile("cp.async.commit_group;" ::: "memory");
}
template<int N> __device__ __forceinline__ void cp_wait(){
    asm volatile("cp.async.wait_group %0;" :: "n"(N) : "memory");
}
__device__ __forceinline__ void ldm_x4(uint32_t a, uint32_t& r0, uint32_t& r1,
                                       uint32_t& r2, uint32_t& r3){
    asm volatile("ldmatrix.sync.aligned.m8n8.x4.shared.b16 {%0,%1,%2,%3}, [%4];"
                 : "=r"(r0), "=r"(r1), "=r"(r2), "=r"(r3) : "r"(a));
}
__device__ __forceinline__ void ldm_x4_t(uint32_t a, uint32_t& r0, uint32_t& r1,
                                         uint32_t& r2, uint32_t& r3){
    asm volatile("ldmatrix.sync.aligned.m8n8.x4.trans.shared.b16 {%0,%1,%2,%3}, [%4];"
                 : "=r"(r0), "=r"(r1), "=r"(r2), "=r"(r3) : "r"(a));
}
__device__ __forceinline__ void mma_f16(float* c, const uint32_t* a,
                                        uint32_t b0, uint32_t b1){
    asm volatile(
      "mma.sync.aligned.m16n8k16.row.col.f32.f16.f16.f32 "
      "{%0,%1,%2,%3}, {%4,%5,%6,%7}, {%8,%9}, {%0,%1,%2,%3};"
      : "+f"(c[0]), "+f"(c[1]), "+f"(c[2]), "+f"(c[3])
      : "r"(a[0]), "r"(a[1]), "r"(a[2]), "r"(a[3]), "r"(b0), "r"(b1));
}
__device__ __forceinline__ uint32_t pkh(float a, float b){
    __half2 t = __floats2half2_rn(a, b);
    return *(uint32_t*)&t;
}

// ============================================================================
// fp16 tensor-core GEMM (R12/R15 configuration — measured optimum, frozen):
// CTA 128x128, 4 warps x 64x64, BK=32, 3-stage cp.async (.ca), persistent.
// ============================================================================
#define GBK 32
#define TILE_B (128 * 80)
#define STAGE_B (2 * TILE_B)
#define GM_SMEM (3 * STAGE_B)    // 61440 bytes
#define GEMM_CTAS 296

__global__ __launch_bounds__(128, 2) void gemm_f16(
    const __half* __restrict__ A, const __half* __restrict__ B,
    const float* __restrict__ bias, float* __restrict__ C,
    __half* __restrict__ Ch,
    int M, int N, int K)
{
    extern __shared__ __align__(16) char smem[];
    const uint32_t sb = smem_u32(smem);

    const int tid  = threadIdx.x;
    const int w    = tid >> 5;
    const int lane = tid & 31;
    const int wm   = (w & 1) * 64;
    const int wn   = (w >> 1) * 64;

    const int tiles_n = N >> 7;
    const int total_tiles = (M >> 7) * tiles_n;

    const int a_row  = lane & 15;
    const int a_koff = (lane >> 4) << 3;
    const int b_row  = (lane & 7) + ((lane >> 4) << 3);
    const int b_koff = ((lane >> 3) & 1) << 3;
    const int nchunks = K / GBK;

    for (int t = blockIdx.x; t < total_tiles; t += gridDim.x) {
        const int bm = (t / tiles_n) << 7;
        const int bn = (t % tiles_n) << 7;
        const __half* gA = A + (size_t)bm * K;
        const __half* gB = B + (size_t)bn * K;

        auto load_stage = [&](int s, int k0){
            const uint32_t dstb = sb + s * STAGE_B;
            const __half* srcs[2] = { gA, gB };
#pragma unroll
            for (int u = 0; u < 2; u++) {
                const __half* g = srcs[u];
                const uint32_t db = dstb + u * TILE_B;
#pragma unroll
                for (int i = 0; i < 4; i++) {
                    const int idx = i * 128 + tid;
                    const int row = idx >> 2;
                    const int kq  = idx & 3;
                    cp16(db + row * 80 + kq * 16, g + (size_t)row * K + k0 + kq * 8);
                }
            }
            cp_commit();
        };

        float acc[4][8][4];
#pragma unroll
        for (int mt = 0; mt < 4; mt++)
#pragma unroll
            for (int nt = 0; nt < 8; nt++)
#pragma unroll
                for (int r = 0; r < 4; r++) acc[mt][nt][r] = 0.f;

        __syncthreads();
        load_stage(0, 0);
        load_stage(1, GBK);

        int stage = 0;
        for (int ic = 0; ic < nchunks; ic++) {
            cp_wait<1>();
            __syncthreads();
            if (ic + 2 < nchunks) {
                int s2 = stage + 2; if (s2 >= 3) s2 -= 3;
                load_stage(s2, (ic + 2) * GBK);
            } else {
                cp_commit();
            }

            const uint32_t st = sb + stage * STAGE_B;
            const uint32_t sA = st;
            const uint32_t sB = st + TILE_B;

#pragma unroll
            for (int ks = 0; ks < 2; ks++) {
                const int kb = ks * 16;
                uint32_t af[4][4];
#pragma unroll
                for (int mt = 0; mt < 4; mt++) {
                    const uint32_t aoff =
                        (uint32_t)((wm + mt * 16 + a_row) * 80 + (kb + a_koff) * 2);
                    ldm_x4(sA + aoff, af[mt][0], af[mt][1], af[mt][2], af[mt][3]);
                }
#pragma unroll
                for (int np = 0; np < 4; np++) {
                    const uint32_t boff =
                        (uint32_t)((wn + np * 16 + b_row) * 80 + (kb + b_koff) * 2);
                    uint32_t b0, b1, b2, b3;
                    ldm_x4(sB + boff, b0, b1, b2, b3);
#pragma unroll
                    for (int mt = 0; mt < 4; mt++) {
                        mma_f16(acc[mt][2*np],   af[mt], b0, b1);
                        mma_f16(acc[mt][2*np+1], af[mt], b2, b3);
                    }
                }
            }
            stage++; if (stage >= 3) stage -= 3;
        }
        cp_wait<0>();

#pragma unroll
        for (int mt = 0; mt < 4; mt++) {
            const int r0 = bm + wm + mt * 16 + (lane >> 2);
#pragma unroll
            for (int nt = 0; nt < 8; nt++) {
                const int col = bn + wn + nt * 8 + ((lane & 3) << 1);
                const float2 bv = *(const float2*)&bias[col];
                float v0 = acc[mt][nt][0] + bv.x, v1 = acc[mt][nt][1] + bv.y;
                float v2 = acc[mt][nt][2] + bv.x, v3 = acc[mt][nt][3] + bv.y;
                if (Ch) {
                    *(uint32_t*)(Ch + (size_t)r0       * N + col) = pkh(v0, v1);
                    *(uint32_t*)(Ch + (size_t)(r0 + 8) * N + col) = pkh(v2, v3);
                } else {
                    *(float2*)&C[(size_t)r0       * N + col] = make_float2(v0, v1);
                    *(float2*)&C[(size_t)(r0 + 8) * N + col] = make_float2(v2, v3);
                }
            }
        }
    }
}

// ============================================================================
// RoPE, vectorized: one thread per (t, head, q|k) rotates all 16 pairs.
// 64-byte contiguous segment per thread, same arithmetic as before.
// ============================================================================
__global__ void rope_f16_kernel(__half* __restrict__ qkv)
{
    int idx = blockIdx.x * blockDim.x + threadIdx.x;   // SEQ*NH*2 total
    if (idx >= SEQ * NH * 2) return;
    const int qk = idx & 1;
    const int h  = (idx >> 1) & 31;
    const int t  = idx >> 6;

    __half* base = qkv + (size_t)t * QKV_N + qk * DIMS + h * HD;
    union { __half h16[32]; uint4 v[4]; } buf;
    buf.v[0] = *(const uint4*)(base);
    buf.v[1] = *(const uint4*)(base + 8);
    buf.v[2] = *(const uint4*)(base + 16);
    buf.v[3] = *(const uint4*)(base + 24);

#pragma unroll
    for (int d = 0; d < 16; d++) {
        const float freq  = __expf(-(float)d * 0.5756462732485115f); // ln(1e4)/16
        const float theta = (float)t * freq;
        float s, c;
        sincosf(theta, &s, &c);
        float x1 = __half2float(buf.h16[d]);
        float x2 = __half2float(buf.h16[d + 16]);
        buf.h16[d]      = __float2half_rn(x1 * c - x2 * s);
        buf.h16[d + 16] = __float2half_rn(x1 * s + x2 * c);
    }

    *(uint4*)(base)      = buf.v[0];
    *(uint4*)(base + 8)  = buf.v[1];
    *(uint4*)(base + 16) = buf.v[2];
    *(uint4*)(base + 24) = buf.v[3];
}

// ============================================================================
// Tensor-core flash attention, causal, fp16, 32-row warp tiles.
// CTA = (head, 128 q-rows), 128 threads = 4 warps x 32 rows x 64 keys.
// K/V fragments amortized over 2x MMAs (LDS traffic -44%). 2 CTAs/SM.
// ============================================================================
#define AP      88
#define SQH     0
#define STG0    (128*AP)
#define STG_SZ  (2*64*AP)
#define KH_OFF  0
#define VH_OFF  (64*AP)
#define ATT_SMEM ((STG0 + 2*STG_SZ) * 2) // 67584 bytes

#define C2EXP (0.11180339887498949f * 1.4426950408889634f)

__global__ __launch_bounds__(128, 2) void attn_f16(
    const __half* __restrict__ qkvh,
    __half* __restrict__ aoh)
{
    extern __shared__ __align__(16) __half smA[];
    const uint32_t sb = smem_u32(smA);
    const int h  = blockIdx.x;
    const int qb = (gridDim.y - 1) - blockIdx.y;   // heavy tiles first
    const int tid = threadIdx.x, lane = tid & 31, w = tid >> 5;
    const int q0 = qb * 128;

    // ---- Q load (128 rows x 10 col-chunks, 1280 chunks, 128 threads) ----
    {
        const size_t off = (size_t)q0 * QKV_N + h * HD;
#pragma unroll
        for (int it = 0; it < 10; it++) {
            const int idx = it * 128 + tid;
            const int row = idx / 10, col = idx % 10;
            cp16(sb + (SQH + row * AP) * 2 + col * 16,
                 qkvh + off + (size_t)row * QKV_N + col * 8);
        }
    }
    auto loadKV = [&](int kb, int s){
        const size_t koff = (size_t)(kb * 64) * QKV_N + DIMS + h * HD;
        const uint32_t stg = sb + (STG0 + s * STG_SZ) * 2;
#pragma unroll
        for (int it = 0; it < 5; it++) {
            const int idx = it * 128 + tid;       // 640 pairs exactly
            const int row = idx / 10, col = idx % 10;
            const size_t gk = koff + (size_t)row * QKV_N + col * 8;
            cp16(stg + (KH_OFF + row * AP) * 2 + col * 16, qkvh + gk);
            cp16(stg + (VH_OFF + row * AP) * 2 + col * 16, qkvh + gk + DIMS);
        }
    };

    float of[2][10][4];
#pragma unroll
    for (int mt = 0; mt < 2; mt++)
#pragma unroll
        for (int i = 0; i < 10; i++)
#pragma unroll
            for (int j = 0; j < 4; j++) of[mt][i][j] = 0.f;
    float mA[2] = {-1e30f, -1e30f}, mB[2] = {-1e30f, -1e30f};
    float lA[2] = {0.f, 0.f},       lB[2] = {0.f, 0.f};

    loadKV(0, 0);
    cp_commit();

    const int a_row  = lane & 15;
    const int a_k    = (lane >> 4) << 3;
    const int b_row  = (lane & 7) + ((lane >> 4) << 3);
    const int b_k    = ((lane >> 3) & 1) << 3;
    const int vk     = (lane & 7) + (((lane >> 3) & 1) << 3);
    const int vd     = (lane >> 4) << 3;
    const int clb    = 2 * (lane & 3);
    const int rq     = lane >> 2;              // quad row 0..7

    const int ntiles = 2 * qb + 2;
    for (int kb = 0; kb < ntiles; kb++) {
        cp_wait<0>();
        __syncthreads();
        if (kb + 1 < ntiles) { loadKV(kb + 1, (kb + 1) & 1); cp_commit(); }

        // warp-level full-mask skip: all this warp's 32 rows < first key col
        if (kb * 64 > q0 + w * 32 + 31) continue;

        const uint32_t stg = sb + (STG0 + (kb & 1) * STG_SZ) * 2;

        // ---- S = Q K^T (raw units), 2 m-tiles per warp ----
        float sf[2][8][4];
#pragma unroll
        for (int mt = 0; mt < 2; mt++)
#pragma unroll
            for (int i = 0; i < 8; i++)
#pragma unroll
                for (int j = 0; j < 4; j++) sf[mt][i][j] = 0.f;

#pragma unroll
        for (int kc = 0; kc < 5; kc++) {
            uint32_t aq[2][4];
#pragma unroll
            for (int mt = 0; mt < 2; mt++) {
                const uint32_t aoff =
                    (uint32_t)((w * 32 + mt * 16 + a_row) * AP + kc * 16 + a_k) * 2;
                ldm_x4(sb + SQH * 2 + aoff, aq[mt][0], aq[mt][1], aq[mt][2], aq[mt][3]);
            }
#pragma unroll
            for (int bp = 0; bp < 4; bp++) {
                const uint32_t boff = (uint32_t)((bp * 16 + b_row) * AP + kc * 16 + b_k) * 2;
                uint32_t b0, b1, b2, b3;
                ldm_x4(stg + KH_OFF * 2 + boff, b0, b1, b2, b3);
#pragma unroll
                for (int mt = 0; mt < 2; mt++) {
                    mma_f16(sf[mt][2*bp],   aq[mt], b0, b1);
                    mma_f16(sf[mt][2*bp+1], aq[mt], b2, b3);
                }
            }
        }

        // ---- causal mask (raw units), per m-tile ----
#pragma unroll
        for (int mt = 0; mt < 2; mt++) {
            const int rbase = q0 + w * 32 + mt * 16 + rq;
            const bool needmask = (kb * 64 + 63 > rbase - rq + 0 + (w*0) + (q0*0) + (rbase - rbase) + (kb*0) + (q0 + w * 32 + mt * 16));
            // simplified: mask needed when last key col can exceed smallest row
            if (kb * 64 + 63 > q0 + w * 32 + mt * 16) {
#pragma unroll
                for (int nt = 0; nt < 8; nt++) {
                    const int c0 = kb * 64 + nt * 8 + clb;
                    const int grA = rbase, grB = rbase + 8;
#pragma unroll
                    for (int j = 0; j < 2; j++) {
                        if (c0 + j > grA) sf[mt][nt][j]     = -1e30f;
                        if (c0 + j > grB) sf[mt][nt][2 + j] = -1e30f;
                    }
                }
            }
            (void)needmask;
        }

        // ---- online softmax per m-tile ----
#pragma unroll
        for (int mt = 0; mt < 2; mt++) {
            float mxA = -1e30f, mxB = -1e30f;
#pragma unroll
            for (int nt = 0; nt < 8; nt++) {
                mxA = fmaxf(mxA, fmaxf(sf[mt][nt][0], sf[mt][nt][1]));
                mxB = fmaxf(mxB, fmaxf(sf[mt][nt][2], sf[mt][nt][3]));
            }
            mxA = fmaxf(mxA, __shfl_xor_sync(0xffffffffu, mxA, 1));
            mxA = fmaxf(mxA, __shfl_xor_sync(0xffffffffu, mxA, 2));
            mxB = fmaxf(mxB, __shfl_xor_sync(0xffffffffu, mxB, 1));
            mxB = fmaxf(mxB, __shfl_xor_sync(0xffffffffu, mxB, 2));
            const float mnA = fmaxf(mA[mt], mxA), mnB = fmaxf(mB[mt], mxB);
            const float alphaA = exp2f((mA[mt] - mnA) * C2EXP);
            const float alphaB = exp2f((mB[mt] - mnB) * C2EXP);
            mA[mt] = mnA; mB[mt] = mnB;
            const float cA = -mnA * C2EXP, cB = -mnB * C2EXP;

            float sA = 0.f, sB = 0.f;
#pragma unroll
            for (int nt = 0; nt < 8; nt++) {
#pragma unroll
                for (int j = 0; j < 2; j++) {
                    float pA = exp2f(fmaf(sf[mt][nt][j],     C2EXP, cA));
                    float pB = exp2f(fmaf(sf[mt][nt][2 + j], C2EXP, cB));
                    sf[mt][nt][j] = pA; sf[mt][nt][2 + j] = pB;
                    sA += pA; sB += pB;
                }
            }
            sA += __shfl_xor_sync(0xffffffffu, sA, 1);
            sA += __shfl_xor_sync(0xffffffffu, sA, 2);
            sB += __shfl_xor_sync(0xffffffffu, sB, 1);
            sB += __shfl_xor_sync(0xffffffffu, sB, 2);
            lA[mt] = lA[mt] * alphaA + sA;
            lB[mt] = lB[mt] * alphaB + sB;
#pragma unroll
            for (int d = 0; d < 10; d++) {
                of[mt][d][0] *= alphaA; of[mt][d][1] *= alphaA;
                of[mt][d][2] *= alphaB; of[mt][d][3] *= alphaB;
            }
        }

        // ---- O += P V, V fragments shared across both m-tiles ----
#pragma unroll
        for (int kc2 = 0; kc2 < 4; kc2++) {
            uint32_t aP[2][4];
#pragma unroll
            for (int mt = 0; mt < 2; mt++) {
#pragma unroll
                for (int half = 0; half < 2; half++) {
                    const int nt = 2 * kc2 + half;
                    aP[mt][half * 2 + 0] = pkh(sf[mt][nt][0], sf[mt][nt][1]);
                    aP[mt][half * 2 + 1] = pkh(sf[mt][nt][2], sf[mt][nt][3]);
                }
            }
#pragma unroll
            for (int dp = 0; dp < 5; dp++) {
                const uint32_t voff = (uint32_t)((kc2 * 16 + vk) * AP + dp * 16 + vd) * 2;
                uint32_t v0, v1, v2, v3;
                ldm_x4_t(stg + VH_OFF * 2 + voff, v0, v1, v2, v3);
#pragma unroll
                for (int mt = 0; mt < 2; mt++) {
                    mma_f16(of[mt][2*dp],   aP[mt], v0, v1);
                    mma_f16(of[mt][2*dp+1], aP[mt], v2, v3);
                }
            }
        }
    }

    // ---- epilogue: normalize, store fp16, per m-tile ----
    const int colb = h * HD + clb;
#pragma unroll
    for (int mt = 0; mt < 2; mt++) {
        const float iA = 1.f / lA[mt], iB = 1.f / lB[mt];
        const int gA = q0 + w * 32 + mt * 16 + rq;
#pragma unroll
        for (int nt = 0; nt < 10; nt++) {
            const int col = colb + nt * 8;
            *(uint32_t*)(aoh + (size_t)gA * DIMS + col)       =
                pkh(of[mt][nt][0] * iA, of[mt][nt][1] * iA);
            *(uint32_t*)(aoh + (size_t)(gA + 8) * DIMS + col) =
                pkh(of[mt][nt][2] * iB, of[mt][nt][3] * iB);
        }
    }
}

// ============================================================================
extern "C" void kernel_launch(void* const* d_in, const int* in_sizes, int n_in,
                              void* d_out, int out_size)
{
    const float* x       = (const float*)d_in[0];
    const float* Wqkv_w  = (const float*)d_in[1];
    const float* Wqkv_b  = (const float*)d_in[2];
    const float* out_w   = (const float*)d_in[3];
    const float* out_b   = (const float*)d_in[4];
    // d_in[5] = mask: causal triu(-1e9), implemented structurally; unused.
    float* outp = (float*)d_out;

    __half *xh, *w1h, *w2h, *aoh, *qkvh;
    cudaGetSymbolAddress((void**)&xh,   g_xh);
    cudaGetSymbolAddress((void**)&w1h,  g_w1h);
    cudaGetSymbolAddress((void**)&w2h,  g_w2h);
    cudaGetSymbolAddress((void**)&aoh,  g_aoh);
    cudaGetSymbolAddress((void**)&qkvh, g_qkvh);

    cudaFuncSetAttribute(gemm_f16,
                         cudaFuncAttributeMaxDynamicSharedMemorySize, GM_SMEM);
    cudaFuncSetAttribute(attn_f16,
                         cudaFuncAttributeMaxDynamicSharedMemorySize, ATT_SMEM);

    // 0) fused fp16 conversions of x and both weights (single launch)
    {
        cvt_all_kernel<<<(N4_TOTAL + 255) / 256, 256>>>(x, Wqkv_w, out_w,
                                                        xh, w1h, w2h);
    }
    // 1) QKV projection -> fp16 qkv directly (persistent tiles)
    {
        gemm_f16<<<GEMM_CTAS, 128, GM_SMEM>>>(xh, w1h, Wqkv_b, nullptr, qkvh,
                                              SEQ, QKV_N, DIMS);
    }
    // 2) RoPE on q,k (in place, fp16, vectorized)
    {
        int total = SEQ * NH * 2;
        rope_f16_kernel<<<(total + 255) / 256, 256>>>(qkvh);
    }
    // 3) tensor-core causal flash attention -> fp16 attn out
    {
        dim3 grid(NH, SEQ / 128);
        attn_f16<<<grid, 128, ATT_SMEM>>>(qkvh, aoh);
    }
    // 4) output projection -> fp32 final output (persistent tiles)
    {
        gemm_f16<<<GEMM_CTAS, 128, GM_SMEM>>>(aoh, w2h, out_b, outp, nullptr,
                                              SEQ, DIMS, DIMS);
    }
}